// round 2
// baseline (speedup 1.0000x reference)
#include <cuda_runtime.h>

#define N_NODES 32000
#define N_EDGES 512000
#define LATENT 32
#define HID 128
#define HSTR 132          // padded hidden row stride (floats) to dodge bank conflicts

// ---------------- persistent scratch (device globals; no allocation) ----------------
__device__ float g_node[N_NODES * LATENT];
__device__ float g_edge[N_EDGES * LATENT];
__device__ float g_agg [N_NODES * LATENT];

// ---------------- packed f32x2 helpers ----------------
__device__ __forceinline__ unsigned long long pack2(float lo, float hi) {
    unsigned long long r;
    asm("mov.b64 %0, {%1, %2};" : "=l"(r) : "r"(__float_as_uint(lo)), "r"(__float_as_uint(hi)));
    return r;
}
__device__ __forceinline__ unsigned long long fma2(unsigned long long a, unsigned long long b,
                                                   unsigned long long c) {
    unsigned long long d;
    asm("fma.rn.f32x2 %0, %1, %2, %3;" : "=l"(d) : "l"(a), "l"(b), "l"(c));
    return d;
}
__device__ __forceinline__ float2 unpack2(unsigned long long v) {
    unsigned int lo, hi;
    asm("mov.b64 {%0, %1}, %2;" : "=r"(lo), "=r"(hi) : "l"(v));
    return make_float2(__uint_as_float(lo), __uint_as_float(hi));
}
__device__ __forceinline__ float f4c(const float4& v, int i) {
    return i == 0 ? v.x : (i == 1 ? v.y : (i == 2 ? v.z : v.w));
}

// ---------------- GEMM layer: [32 x K] @ [K x 128] -> relu -> smem [32 x HSTR] ----------------
// 128 threads: thread = (rowg = tid>>4 -> 4 rows, colg = tid&15 -> 8 cols)
// Accumulators: 16 f32x2 pairs = 4 rows x 8 cols.
template<int K, int XSTR, bool VEC>
__device__ __forceinline__ void layer128(const float* __restrict__ Xs,
                                         const float* __restrict__ W,
                                         float* __restrict__ Out, int tid) {
    const int r0 = (tid >> 4) * 4;
    const int c0 = (tid & 15) * 8;
    unsigned long long acc[16];
#pragma unroll
    for (int i = 0; i < 16; i++) acc[i] = 0ull;

    if (VEC) {
#pragma unroll 2
        for (int k4 = 0; k4 < K / 4; k4++) {
            float4 a0 = *(const float4*)(Xs + (r0 + 0) * XSTR + k4 * 4);
            float4 a1 = *(const float4*)(Xs + (r0 + 1) * XSTR + k4 * 4);
            float4 a2 = *(const float4*)(Xs + (r0 + 2) * XSTR + k4 * 4);
            float4 a3 = *(const float4*)(Xs + (r0 + 3) * XSTR + k4 * 4);
#pragma unroll
            for (int kk = 0; kk < 4; kk++) {
                const float* wr = W + (k4 * 4 + kk) * HID + c0;
                ulonglong2 wA = *(const ulonglong2*)(wr);
                ulonglong2 wB = *(const ulonglong2*)(wr + 4);
                unsigned long long p0 = pack2(f4c(a0, kk), f4c(a0, kk));
                unsigned long long p1 = pack2(f4c(a1, kk), f4c(a1, kk));
                unsigned long long p2 = pack2(f4c(a2, kk), f4c(a2, kk));
                unsigned long long p3 = pack2(f4c(a3, kk), f4c(a3, kk));
                acc[0]  = fma2(p0, wA.x, acc[0]);  acc[1]  = fma2(p0, wA.y, acc[1]);
                acc[2]  = fma2(p0, wB.x, acc[2]);  acc[3]  = fma2(p0, wB.y, acc[3]);
                acc[4]  = fma2(p1, wA.x, acc[4]);  acc[5]  = fma2(p1, wA.y, acc[5]);
                acc[6]  = fma2(p1, wB.x, acc[6]);  acc[7]  = fma2(p1, wB.y, acc[7]);
                acc[8]  = fma2(p2, wA.x, acc[8]);  acc[9]  = fma2(p2, wA.y, acc[9]);
                acc[10] = fma2(p2, wB.x, acc[10]); acc[11] = fma2(p2, wB.y, acc[11]);
                acc[12] = fma2(p3, wA.x, acc[12]); acc[13] = fma2(p3, wA.y, acc[13]);
                acc[14] = fma2(p3, wB.x, acc[14]); acc[15] = fma2(p3, wB.y, acc[15]);
            }
        }
    } else {
#pragma unroll
        for (int k = 0; k < K; k++) {
            float a0 = Xs[(r0 + 0) * XSTR + k];
            float a1 = Xs[(r0 + 1) * XSTR + k];
            float a2 = Xs[(r0 + 2) * XSTR + k];
            float a3 = Xs[(r0 + 3) * XSTR + k];
            const float* wr = W + k * HID + c0;
            ulonglong2 wA = *(const ulonglong2*)(wr);
            ulonglong2 wB = *(const ulonglong2*)(wr + 4);
            unsigned long long p0 = pack2(a0, a0);
            unsigned long long p1 = pack2(a1, a1);
            unsigned long long p2 = pack2(a2, a2);
            unsigned long long p3 = pack2(a3, a3);
            acc[0]  = fma2(p0, wA.x, acc[0]);  acc[1]  = fma2(p0, wA.y, acc[1]);
            acc[2]  = fma2(p0, wB.x, acc[2]);  acc[3]  = fma2(p0, wB.y, acc[3]);
            acc[4]  = fma2(p1, wA.x, acc[4]);  acc[5]  = fma2(p1, wA.y, acc[5]);
            acc[6]  = fma2(p1, wB.x, acc[6]);  acc[7]  = fma2(p1, wB.y, acc[7]);
            acc[8]  = fma2(p2, wA.x, acc[8]);  acc[9]  = fma2(p2, wA.y, acc[9]);
            acc[10] = fma2(p2, wB.x, acc[10]); acc[11] = fma2(p2, wB.y, acc[11]);
            acc[12] = fma2(p3, wA.x, acc[12]); acc[13] = fma2(p3, wA.y, acc[13]);
            acc[14] = fma2(p3, wB.x, acc[14]); acc[15] = fma2(p3, wB.y, acc[15]);
        }
    }
    // relu + store
#pragma unroll
    for (int r = 0; r < 4; r++) {
        float2 v0 = unpack2(acc[r * 4 + 0]);
        float2 v1 = unpack2(acc[r * 4 + 1]);
        float2 v2 = unpack2(acc[r * 4 + 2]);
        float2 v3 = unpack2(acc[r * 4 + 3]);
        float4 o0 = make_float4(fmaxf(v0.x, 0.f), fmaxf(v0.y, 0.f), fmaxf(v1.x, 0.f), fmaxf(v1.y, 0.f));
        float4 o1 = make_float4(fmaxf(v2.x, 0.f), fmaxf(v2.y, 0.f), fmaxf(v3.x, 0.f), fmaxf(v3.y, 0.f));
        *(float4*)(Out + (r0 + r) * HSTR + c0)     = o0;
        *(float4*)(Out + (r0 + r) * HSTR + c0 + 4) = o1;
    }
}

// ---------------- last layer: [32 x 128] @ [128 x 32] -> out (no relu) ----------------
// thread = (row = tid>>2, 8 cols at (tid&3)*8)
__device__ __forceinline__ void layer_out32(const float* __restrict__ Hs,
                                            const float* __restrict__ W,
                                            float out[8], int tid) {
    const int row = tid >> 2;
    const int c0  = (tid & 3) * 8;
    unsigned long long acc[4] = {0ull, 0ull, 0ull, 0ull};
#pragma unroll 4
    for (int k4 = 0; k4 < HID / 4; k4++) {
        float4 a = *(const float4*)(Hs + row * HSTR + k4 * 4);
#pragma unroll
        for (int kk = 0; kk < 4; kk++) {
            const float* wr = W + (k4 * 4 + kk) * 32 + c0;
            ulonglong2 wA = *(const ulonglong2*)(wr);
            ulonglong2 wB = *(const ulonglong2*)(wr + 4);
            unsigned long long ap = pack2(f4c(a, kk), f4c(a, kk));
            acc[0] = fma2(ap, wA.x, acc[0]);
            acc[1] = fma2(ap, wA.y, acc[1]);
            acc[2] = fma2(ap, wB.x, acc[2]);
            acc[3] = fma2(ap, wB.y, acc[3]);
        }
    }
#pragma unroll
    for (int p = 0; p < 4; p++) {
        float2 v = unpack2(acc[p]);
        out[p * 2 + 0] = v.x;
        out[p * 2 + 1] = v.y;
    }
}

// ---------------- encoder: in[rows x IN] -> MLP(IN->128->128->32) -> dst ----------------
template<int DST>  // 0 = g_node, 1 = g_edge
__global__ void __launch_bounds__(128) enc_kernel(const float* __restrict__ in,
                                                  const float* __restrict__ w0,
                                                  const float* __restrict__ w1,
                                                  const float* __restrict__ w2) {
    __shared__ float Xs[32][4];
    __shared__ float H1[32][HSTR];
    __shared__ float H2[32][HSTR];
    const int tid = threadIdx.x;
    const int b0  = blockIdx.x * 32;
    if (tid < 96) {
        int row = tid / 3, c = tid % 3;
        Xs[row][c] = in[(b0 + row) * 3 + c];
    }
    __syncthreads();
    layer128<3, 4, false>(&Xs[0][0], w0, &H1[0][0], tid);
    __syncthreads();
    layer128<128, HSTR, true>(&H1[0][0], w1, &H2[0][0], tid);
    __syncthreads();
    float out[8];
    layer_out32(&H2[0][0], w2, out, tid);
    const int row = tid >> 2, c0 = (tid & 3) * 8;
    float* dst = (DST == 0 ? g_node : g_edge);
    float4 o0 = make_float4(out[0], out[1], out[2], out[3]);
    float4 o1 = make_float4(out[4], out[5], out[6], out[7]);
    *(float4*)(dst + (b0 + row) * LATENT + c0)     = o0;
    *(float4*)(dst + (b0 + row) * LATENT + c0 + 4) = o1;
}

// ---------------- edge update: e_in=[edge|node[s]|node[r]] -> MLP(96->128->128->32)+res,
// plus fused segment_sum scatter into g_agg ----------------
__global__ void __launch_bounds__(128) edge_kernel(const int* __restrict__ gi,
                                                   const float* __restrict__ w0,
                                                   const float* __restrict__ w1,
                                                   const float* __restrict__ w2) {
    __shared__ float Xs[32][100];
    __shared__ float H1[32][HSTR];
    __shared__ float H2[32][HSTR];
    __shared__ int   sidx[32][2];
    const int tid = threadIdx.x;
    const int e0  = blockIdx.x * 32;
    if (tid < 64) sidx[tid >> 1][tid & 1] = gi[(e0 + (tid >> 1)) * 2 + (tid & 1)];
    __syncthreads();
    {
        const int row = tid >> 2, j = tid & 3;
        const int e = e0 + row, s = sidx[row][0], r = sidx[row][1];
#pragma unroll
        for (int p = 0; p < 6; p++) {
            int col = (j + p * 4) * 4;  // 0..92
            float4 v;
            if (col < 32)      v = *(const float4*)(g_edge + e * LATENT + col);
            else if (col < 64) v = *(const float4*)(g_node + s * LATENT + (col - 32));
            else               v = *(const float4*)(g_node + r * LATENT + (col - 64));
            *(float4*)(&Xs[row][col]) = v;
        }
    }
    __syncthreads();
    layer128<96, 100, true>(&Xs[0][0], w0, &H1[0][0], tid);
    __syncthreads();
    layer128<128, HSTR, true>(&H1[0][0], w1, &H2[0][0], tid);
    __syncthreads();
    float out[8];
    layer_out32(&H2[0][0], w2, out, tid);
    const int row = tid >> 2, c0 = (tid & 3) * 8;
    const int e = e0 + row, rcv = sidx[row][1];
    float v[8];
#pragma unroll
    for (int j = 0; j < 8; j++) v[j] = out[j] + Xs[row][c0 + j];  // residual
    *(float4*)(g_edge + e * LATENT + c0)     = make_float4(v[0], v[1], v[2], v[3]);
    *(float4*)(g_edge + e * LATENT + c0 + 4) = make_float4(v[4], v[5], v[6], v[7]);
#pragma unroll
    for (int j = 0; j < 8; j++) atomicAdd(&g_agg[rcv * LATENT + c0 + j], v[j]);
}

// ---------------- node update: n_in=[node|agg] -> MLP(64->128->128->32)+res ----------------
__global__ void __launch_bounds__(128) node_kernel(const float* __restrict__ w0,
                                                   const float* __restrict__ w1,
                                                   const float* __restrict__ w2) {
    __shared__ float Xs[32][68];
    __shared__ float H1[32][HSTR];
    __shared__ float H2[32][HSTR];
    const int tid = threadIdx.x;
    const int n0  = blockIdx.x * 32;
    {
        const int row = tid >> 2, j = tid & 3;
        const int n = n0 + row;
#pragma unroll
        for (int p = 0; p < 4; p++) {
            int col = (j + p * 4) * 4;  // 0..60
            float4 v;
            if (col < 32) v = *(const float4*)(g_node + n * LATENT + col);
            else          v = *(const float4*)(g_agg  + n * LATENT + (col - 32));
            *(float4*)(&Xs[row][col]) = v;
        }
    }
    __syncthreads();
    layer128<64, 68, true>(&Xs[0][0], w0, &H1[0][0], tid);
    __syncthreads();
    layer128<128, HSTR, true>(&H1[0][0], w1, &H2[0][0], tid);
    __syncthreads();
    float out[8];
    layer_out32(&H2[0][0], w2, out, tid);
    const int row = tid >> 2, c0 = (tid & 3) * 8;
    const int n = n0 + row;
    float v[8];
#pragma unroll
    for (int j = 0; j < 8; j++) v[j] = out[j] + Xs[row][c0 + j];
    *(float4*)(g_node + n * LATENT + c0)     = make_float4(v[0], v[1], v[2], v[3]);
    *(float4*)(g_node + n * LATENT + c0 + 4) = make_float4(v[4], v[5], v[6], v[7]);
}

// ---------------- decoder: node -> MLP(32->128->128->1) ----------------
__global__ void __launch_bounds__(128) dec_kernel(const float* __restrict__ w0,
                                                  const float* __restrict__ w1,
                                                  const float* __restrict__ w2,
                                                  float* __restrict__ out) {
    __shared__ float Xs[32][36];
    __shared__ float H1[32][HSTR];
    __shared__ float H2[32][HSTR];
    const int tid = threadIdx.x;
    const int b0  = blockIdx.x * 32;
    {
        const int row = tid >> 2, j = tid & 3;
#pragma unroll
        for (int p = 0; p < 2; p++) {
            int col = (j + p * 4) * 4;  // 0..28
            *(float4*)(&Xs[row][col]) = *(const float4*)(g_node + (b0 + row) * LATENT + col);
        }
    }
    __syncthreads();
    layer128<32, 36, true>(&Xs[0][0], w0, &H1[0][0], tid);
    __syncthreads();
    layer128<128, HSTR, true>(&H1[0][0], w1, &H2[0][0], tid);
    __syncthreads();
    if (tid < 32) {
        float acc = 0.f;
#pragma unroll 8
        for (int k4 = 0; k4 < HID / 4; k4++) {
            float4 a = *(const float4*)(&H2[tid][k4 * 4]);
            float4 w = *(const float4*)(w2 + k4 * 4);   // dec_w2 is [128,1] = contiguous 128
            acc = fmaf(a.x, w.x, acc);
            acc = fmaf(a.y, w.y, acc);
            acc = fmaf(a.z, w.z, acc);
            acc = fmaf(a.w, w.w, acc);
        }
        out[b0 + tid] = acc;
    }
}

__global__ void zero_agg_kernel() {
    int i = blockIdx.x * 256 + threadIdx.x;           // 1000 x 256 = 256000 float4 = 1.024M floats
    ((float4*)g_agg)[i] = make_float4(0.f, 0.f, 0.f, 0.f);
}

// ---------------- launch ----------------
extern "C" void kernel_launch(void* const* d_in, const int* in_sizes, int n_in,
                              void* d_out, int out_size) {
    const float* input_node = (const float*)d_in[0];
    const float* input_edge = (const float*)d_in[1];
    const int*   gi         = (const int*)d_in[2];
    const float* enc_n_w0 = (const float*)d_in[3];
    const float* enc_n_w1 = (const float*)d_in[4];
    const float* enc_n_w2 = (const float*)d_in[5];
    const float* enc_e_w0 = (const float*)d_in[6];
    const float* enc_e_w1 = (const float*)d_in[7];
    const float* enc_e_w2 = (const float*)d_in[8];
    const float* ep_w0 = (const float*)d_in[9];
    const float* ep_w1 = (const float*)d_in[10];
    const float* ep_w2 = (const float*)d_in[11];
    const float* np_w0 = (const float*)d_in[12];
    const float* np_w1 = (const float*)d_in[13];
    const float* np_w2 = (const float*)d_in[14];
    const float* dec_w0 = (const float*)d_in[15];
    const float* dec_w1 = (const float*)d_in[16];
    const float* dec_w2 = (const float*)d_in[17];
    float* out = (float*)d_out;

    enc_kernel<0><<<N_NODES / 32, 128>>>(input_node, enc_n_w0, enc_n_w1, enc_n_w2);
    enc_kernel<1><<<N_EDGES / 32, 128>>>(input_edge, enc_e_w0, enc_e_w1, enc_e_w2);

    for (int it = 0; it < 4; it++) {
        zero_agg_kernel<<<N_NODES * LATENT / 4 / 256, 256>>>();
        edge_kernel<<<N_EDGES / 32, 128>>>(gi,
                                           ep_w0 + it * 96 * 128,
                                           ep_w1 + it * 128 * 128,
                                           ep_w2 + it * 128 * 32);
        node_kernel<<<N_NODES / 32, 128>>>(np_w0 + it * 64 * 128,
                                           np_w1 + it * 128 * 128,
                                           np_w2 + it * 128 * 32);
    }
    dec_kernel<<<N_NODES / 32, 128>>>(dec_w0, dec_w1, dec_w2, out);
}

// round 8
// speedup vs baseline: 1.2309x; 1.2309x over previous
#include <cuda_runtime.h>
#include <cuda_bf16.h>
#include <mma.h>
#include <stdint.h>

using namespace nvcuda;

#define NN 32000
#define NE 512000

// ---------------- persistent device scratch ----------------
__device__ float g_node[NN * 32];
__device__ float g_edge[NE * 32];
__device__ float g_agg [NN * 32];
__device__ __align__(16) unsigned char g_whi[786432];
__device__ __align__(16) unsigned char g_wlo[786432];

// smem byte offsets
#define A_HI 0
#define A_LO 34816
#define B_HI 69632
#define B_LO 104448
#define S_C  139264          // 128 x 136 fp32 = 69632
#define S_IDX 208896         // 128*2 ints
#define S_W0  209920         // 384 floats
#define SM_DYN 211456
#define ASTR 272             // A/B row stride bytes (136 bf16)
#define CSTR 136             // C scratch row stride (floats)

// pack two bf16: lower k index in lower 16 bits
__device__ __forceinline__ uint32_t packbf(float e_lo, float e_hi) {
    return (uint32_t)__bfloat16_as_ushort(__float2bfloat16(e_lo))
         | ((uint32_t)__bfloat16_as_ushort(__float2bfloat16(e_hi)) << 16);
}
__device__ __forceinline__ void split_pair(float v0, float v1, uint32_t& hi, uint32_t& lo) {
    float h0 = __bfloat162float(__float2bfloat16(v0));
    float h1 = __bfloat162float(__float2bfloat16(v1));
    hi = packbf(v0, v1);
    lo = packbf(v0 - h0, v1 - h1);
}
// store 4 consecutive k-values (k%4==0) of A row as hi/lo bf16
__device__ __forceinline__ void storeA4(char* sm, int row, int k, float x, float y, float z, float w) {
    uint32_t h0, l0, h1, l1;
    split_pair(x, y, h0, l0);
    split_pair(z, w, h1, l1);
    *(uint2*)(sm + A_HI + row * ASTR + k * 2) = make_uint2(h0, h1);
    *(uint2*)(sm + A_LO + row * ASTR + k * 2) = make_uint2(l0, l1);
}

// ---------------- GEMM layer via WMMA: [128 x 16*KSTEPS] @ [16*KSTEPS x 16*NT16] ----------------
// A tiles (hi/lo) row-major ldm 136; B tiles (hi/lo) col-major ldm 136; C -> S_C row-major ldm 136.
// Warp w computes rows [16w, 16w+16). bf16 split: ah*bh + ah*bl + al*bh, fp32 accumulate.
template<int KSTEPS, int NT16>
__device__ __forceinline__ void gemm_wmma(char* sm, int warp) {
    wmma::fragment<wmma::accumulator, 16, 16, 16, float> c[NT16];
#pragma unroll
    for (int j = 0; j < NT16; j++) wmma::fill_fragment(c[j], 0.f);
    const __nv_bfloat16* Ah = (const __nv_bfloat16*)(sm + A_HI) + 16 * warp * CSTR;
    const __nv_bfloat16* Al = (const __nv_bfloat16*)(sm + A_LO) + 16 * warp * CSTR;
    const __nv_bfloat16* Bh = (const __nv_bfloat16*)(sm + B_HI);
    const __nv_bfloat16* Bl = (const __nv_bfloat16*)(sm + B_LO);
#pragma unroll
    for (int ks = 0; ks < KSTEPS; ks++) {
        wmma::fragment<wmma::matrix_a, 16, 16, 16, __nv_bfloat16, wmma::row_major> ah, al;
        wmma::load_matrix_sync(ah, Ah + ks * 16, CSTR);
        wmma::load_matrix_sync(al, Al + ks * 16, CSTR);
#pragma unroll
        for (int j = 0; j < NT16; j++) {
            wmma::fragment<wmma::matrix_b, 16, 16, 16, __nv_bfloat16, wmma::col_major> bh, bl;
            wmma::load_matrix_sync(bh, Bh + j * 16 * CSTR + ks * 16, CSTR);
            wmma::load_matrix_sync(bl, Bl + j * 16 * CSTR + ks * 16, CSTR);
            wmma::mma_sync(c[j], ah, bh, c[j]);
            wmma::mma_sync(c[j], ah, bl, c[j]);
            wmma::mma_sync(c[j], al, bh, c[j]);
        }
    }
    float* C = (float*)(sm + S_C) + 16 * warp * CSTR;
#pragma unroll
    for (int j = 0; j < NT16; j++)
        wmma::store_matrix_sync(C + j * 16, c[j], CSTR, wmma::mem_row_major);
    __syncwarp();   // order C stores before same-warp SIMT reads of the stripe
}

// C (128x128) -> relu -> hi/lo split back into A tile. Thread handles own warp's stripe rows.
__device__ __forceinline__ void resplitA(char* sm, int tid) {
    int row = tid >> 1, seg = tid & 1;
    const float* C = (const float*)(sm + S_C) + row * CSTR + seg * 64;
#pragma unroll
    for (int f = 0; f < 16; f++) {
        float4 v = *(const float4*)(C + f * 4);
        storeA4(sm, row, seg * 64 + f * 4,
                fmaxf(v.x, 0.f), fmaxf(v.y, 0.f), fmaxf(v.z, 0.f), fmaxf(v.w, 0.f));
    }
}

__device__ __forceinline__ void loadB(char* sm, int wd, int cnt16, int tid) {
    const uint4* sH = (const uint4*)(g_whi + wd);
    const uint4* sL = (const uint4*)(g_wlo + wd);
    uint4* dH = (uint4*)(sm + B_HI);
    uint4* dL = (uint4*)(sm + B_LO);
    for (int i = tid; i < cnt16; i += 256) { dH[i] = sH[i]; dL[i] = sL[i]; }
}

// ---------------- weight prep: fp32 -> bf16 hi/lo images, Bt (n-major, k-contiguous) ----------------
struct WPtrs { const float* w[18]; };
__device__ const short P_widx[30] = {4,5,7,8, 9,9,9,9, 10,10,10,10, 11,11,11,11,
                                     12,12,12,12, 13,13,13,13, 14,14,14,14, 15,16};
__device__ const int   P_soff[30] = {0,0,0,0, 0,12288,24576,36864, 0,16384,32768,49152,
                                     0,4096,8192,12288, 0,8192,16384,24576,
                                     0,16384,32768,49152, 0,4096,8192,12288, 0,0};
__device__ const short P_K[30] = {128,128,128,128, 96,96,96,96, 128,128,128,128, 128,128,128,128,
                                  64,64,64,64, 128,128,128,128, 128,128,128,128, 32,128};
__device__ const short P_N[30] = {128,32,128,32, 128,128,128,128, 128,128,128,128, 32,32,32,32,
                                  128,128,128,128, 128,128,128,128, 32,32,32,32, 128,128};
__device__ const int   P_dst[30] = {0,34816,43520,78336,
                                    87040,165376,243712,322048,
                                    121856,200192,278528,356864,
                                    156672,235008,313344,391680,
                                    400384,478720,557056,635392,
                                    435200,513536,591872,670208,
                                    470016,548352,626688,705024,
                                    713728,748544};

__global__ void __launch_bounds__(256) prep_kernel(WPtrs P) {
    int b = blockIdx.x, t = 0, start = 0;
    for (; t < 30; t++) { int nb = (int)P_K[t] * (int)P_N[t] / 256; if (b < start + nb) break; start += nb; }
    int e = (b - start) * 256 + threadIdx.x;
    int N = P_N[t];
    int k = e / N, n = e % N;
    float v = P.w[P_widx[t]][P_soff[t] + e];
    __nv_bfloat16 h = __float2bfloat16(v);
    __nv_bfloat16 l = __float2bfloat16(v - __bfloat162float(h));
    int off = P_dst[t] + n * ASTR + k * 2;
    *(unsigned short*)(g_whi + off) = __bfloat16_as_ushort(h);
    *(unsigned short*)(g_wlo + off) = __bfloat16_as_ushort(l);
}

__global__ void zero_agg_kernel() {
    int i = blockIdx.x * 256 + threadIdx.x;
    ((float4*)g_agg)[i] = make_float4(0.f, 0.f, 0.f, 0.f);
}

// ---------------- fused MLP; MODE: 0=ENC_N 1=ENC_E 2=EDGE 3=NODE 4=DEC ----------------
template<int MODE>
__global__ void __launch_bounds__(256) mlp_mma(const float* __restrict__ in,
                                               const int* __restrict__ gi,
                                               const float* __restrict__ wraw,
                                               float* __restrict__ out,
                                               int wd0, int wd1, int wd2) {
    extern __shared__ char sm[];
    const int tid = threadIdx.x;
    const int warp = tid >> 5;
    const int b0 = blockIdx.x * 128;

    // ---------- build A tile ----------
    if (MODE == 2) {
        ((int*)(sm + S_IDX))[tid] = gi[b0 * 2 + tid];
        __syncthreads();
        int row = tid >> 1, seg = tid & 1;
        int s_ = ((int*)(sm + S_IDX))[row * 2 + 0];
        int r_ = ((int*)(sm + S_IDX))[row * 2 + 1];
#pragma unroll
        for (int f = 0; f < 12; f++) {
            int k = seg * 48 + f * 4;
            const float* src = (k < 32) ? (g_edge + (size_t)(b0 + row) * 32 + k)
                             : (k < 64) ? (g_node + (size_t)s_ * 32 + (k - 32))
                                        : (g_node + (size_t)r_ * 32 + (k - 64));
            float4 v = *(const float4*)src;
            storeA4(sm, row, k, v.x, v.y, v.z, v.w);
        }
    } else if (MODE == 3) {
        int row = tid >> 1, seg = tid & 1;
        const float* base = seg ? (g_agg + (size_t)(b0 + row) * 32) : (g_node + (size_t)(b0 + row) * 32);
#pragma unroll
        for (int f = 0; f < 8; f++) {
            float4 v = *(const float4*)(base + f * 4);
            storeA4(sm, row, seg * 32 + f * 4, v.x, v.y, v.z, v.w);
        }
    } else if (MODE == 4) {
        if (tid < 128) ((float*)(sm + S_W0))[tid] = wraw[tid];
        int row = tid >> 1, seg = tid & 1;
#pragma unroll
        for (int f = 0; f < 4; f++) {
            int k = seg * 16 + f * 4;
            float4 v = *(const float4*)(g_node + (size_t)(b0 + row) * 32 + k);
            storeA4(sm, row, k, v.x, v.y, v.z, v.w);
        }
    } else {  // encoders: SIMT layer0 (3 -> 128) + relu
        for (int i = tid; i < 384; i += 256)            // FIX: 384 floats, 256 threads
            ((float*)(sm + S_W0))[i] = wraw[i];
        __syncthreads();
        int row = tid >> 1, seg = tid & 1;
        float x0 = in[(b0 + row) * 3 + 0];
        float x1 = in[(b0 + row) * 3 + 1];
        float x2 = in[(b0 + row) * 3 + 2];
        const float* W0 = (const float*)(sm + S_W0);
#pragma unroll
        for (int f = 0; f < 16; f++) {
            int c = seg * 64 + f * 4;
            float h0 = fmaxf(fmaf(x0, W0[c + 0], fmaf(x1, W0[128 + c + 0], x2 * W0[256 + c + 0])), 0.f);
            float h1 = fmaxf(fmaf(x0, W0[c + 1], fmaf(x1, W0[128 + c + 1], x2 * W0[256 + c + 1])), 0.f);
            float h2 = fmaxf(fmaf(x0, W0[c + 2], fmaf(x1, W0[128 + c + 2], x2 * W0[256 + c + 2])), 0.f);
            float h3 = fmaxf(fmaf(x0, W0[c + 3], fmaf(x1, W0[128 + c + 3], x2 * W0[256 + c + 3])), 0.f);
            storeA4(sm, row, c, h0, h1, h2, h3);
        }
    }

    const int row = tid >> 1, seg = tid & 1;

    if (MODE == 2 || MODE == 3) {
        loadB(sm, wd0, 128 * 17, tid);
        __syncthreads();
        if (MODE == 2) gemm_wmma<6, 8>(sm, warp);
        else           gemm_wmma<4, 8>(sm, warp);
        resplitA(sm, tid);
        __syncthreads();
        loadB(sm, wd1, 128 * 17, tid);
        __syncthreads();
        gemm_wmma<8, 8>(sm, warp);
        resplitA(sm, tid);
        __syncthreads();
        loadB(sm, wd2, 32 * 17, tid);
        __syncthreads();
        gemm_wmma<8, 2>(sm, warp);
        // epilogue: residual (+ scatter for edges); thread handles (row, cols seg*16..+15)
        const float* C = (const float*)(sm + S_C) + row * CSTR + seg * 16;
        float* dst = (MODE == 2) ? g_edge : g_node;
        float* pe = dst + (size_t)(b0 + row) * 32 + seg * 16;
        int rcv = (MODE == 2) ? ((int*)(sm + S_IDX))[row * 2 + 1] : 0;
        float* pa = g_agg + (size_t)rcv * 32 + seg * 16;
#pragma unroll
        for (int f = 0; f < 4; f++) {
            float4 cc = *(const float4*)(C + f * 4);
            float4 o  = *(const float4*)(pe + f * 4);
            float v0 = cc.x + o.x, v1 = cc.y + o.y, v2 = cc.z + o.z, v3 = cc.w + o.w;
            *(float4*)(pe + f * 4) = make_float4(v0, v1, v2, v3);
            if (MODE == 2) {
                atomicAdd(pa + f * 4 + 0, v0);
                atomicAdd(pa + f * 4 + 1, v1);
                atomicAdd(pa + f * 4 + 2, v2);
                atomicAdd(pa + f * 4 + 3, v3);
            }
        }
    } else if (MODE == 0 || MODE == 1) {
        loadB(sm, wd0, 128 * 17, tid);   // w1: 128x128
        __syncthreads();
        gemm_wmma<8, 8>(sm, warp);
        resplitA(sm, tid);
        __syncthreads();
        loadB(sm, wd1, 32 * 17, tid);    // w2: 128->32
        __syncthreads();
        gemm_wmma<8, 2>(sm, warp);
        const float* C = (const float*)(sm + S_C) + row * CSTR + seg * 16;
        float* dst = ((MODE == 0) ? g_node : g_edge) + (size_t)(b0 + row) * 32 + seg * 16;
#pragma unroll
        for (int f = 0; f < 4; f++)
            *(float4*)(dst + f * 4) = *(const float4*)(C + f * 4);
    } else {  // DEC
        loadB(sm, wd0, 128 * 17, tid);   // w0: 32->128
        __syncthreads();
        gemm_wmma<2, 8>(sm, warp);
        resplitA(sm, tid);
        __syncthreads();
        loadB(sm, wd1, 128 * 17, tid);   // w1: 128x128
        __syncthreads();
        gemm_wmma<8, 8>(sm, warp);
        const float* C = (const float*)(sm + S_C) + row * CSTR + seg * 64;
        const float* W2 = (const float*)(sm + S_W0) + seg * 64;
        float partial = 0.f;
#pragma unroll
        for (int f = 0; f < 16; f++) {
            float4 c4 = *(const float4*)(C + f * 4);
            float4 w4 = *(const float4*)(W2 + f * 4);
            partial = fmaf(fmaxf(c4.x, 0.f), w4.x, partial);
            partial = fmaf(fmaxf(c4.y, 0.f), w4.y, partial);
            partial = fmaf(fmaxf(c4.z, 0.f), w4.z, partial);
            partial = fmaf(fmaxf(c4.w, 0.f), w4.w, partial);
        }
        partial += __shfl_xor_sync(0xFFFFFFFFu, partial, 1);
        if (seg == 0) out[b0 + row] = partial;
    }
}

// ---------------- launch ----------------
extern "C" void kernel_launch(void* const* d_in, const int* in_sizes, int n_in,
                              void* d_out, int out_size) {
    WPtrs P;
    for (int i = 0; i < 18; i++) P.w[i] = (const float*)d_in[i];
    const float* input_node = (const float*)d_in[0];
    const float* input_edge = (const float*)d_in[1];
    const int*   gi         = (const int*)d_in[2];
    float* out = (float*)d_out;

    cudaFuncSetAttribute(mlp_mma<0>, cudaFuncAttributeMaxDynamicSharedMemorySize, SM_DYN);
    cudaFuncSetAttribute(mlp_mma<1>, cudaFuncAttributeMaxDynamicSharedMemorySize, SM_DYN);
    cudaFuncSetAttribute(mlp_mma<2>, cudaFuncAttributeMaxDynamicSharedMemorySize, SM_DYN);
    cudaFuncSetAttribute(mlp_mma<3>, cudaFuncAttributeMaxDynamicSharedMemorySize, SM_DYN);
    cudaFuncSetAttribute(mlp_mma<4>, cudaFuncAttributeMaxDynamicSharedMemorySize, SM_DYN);

    prep_kernel<<<1200, 256>>>(P);

    mlp_mma<0><<<NN / 128, 256, SM_DYN>>>(input_node, nullptr, (const float*)d_in[3], nullptr,
                                          0, 34816, 0);
    mlp_mma<1><<<NE / 128, 256, SM_DYN>>>(input_edge, nullptr, (const float*)d_in[6], nullptr,
                                          43520, 78336, 0);

    for (int it = 0; it < 4; it++) {
        zero_agg_kernel<<<NN * 32 / 4 / 256, 256>>>();
        mlp_mma<2><<<NE / 128, 256, SM_DYN>>>(nullptr, gi, nullptr, nullptr,
                                              87040 + it * 78336,
                                              121856 + it * 78336,
                                              156672 + it * 78336);
        mlp_mma<3><<<NN / 128, 256, SM_DYN>>>(nullptr, nullptr, nullptr, nullptr,
                                              400384 + it * 78336,
                                              435200 + it * 78336,
                                              470016 + it * 78336);
    }
    mlp_mma<4><<<NN / 128, 256, SM_DYN>>>(nullptr, nullptr, (const float*)d_in[17], out,
                                          713728, 748544, 0);
}

// round 9
// speedup vs baseline: 1.3637x; 1.1079x over previous
#include <cuda_runtime.h>
#include <cuda_bf16.h>
#include <mma.h>
#include <stdint.h>

using namespace nvcuda;

#define NN 32000
#define NE 512000

// ---------------- persistent device scratch ----------------
__device__ float g_node[NN * 32];
__device__ float g_edge[NE * 32];
__device__ float g_agg [NN * 32];
__device__ __align__(16) unsigned char g_whi[786432];
__device__ __align__(16) unsigned char g_wlo[786432];

// smem byte offsets (64-row tiles)
#define A_HI 0               // 64 x 272 = 17408
#define A_LO 17408
#define B_HI 34816           // up to 128 n-rows x 272 = 34816
#define B_LO 69632           // C scratch (64 x 136 fp32 = 34816) ALIASES this region
#define S_IDX 104448         // 128 ints
#define S_W0  104960         // 384 floats
#define SM_DYN 106496
#define ASTR 272             // bf16 row stride bytes (136 halves)
#define LDM 136              // half/float leading dim

// pack two bf16: lower k index in lower 16 bits
__device__ __forceinline__ uint32_t packbf(float e_lo, float e_hi) {
    return (uint32_t)__bfloat16_as_ushort(__float2bfloat16(e_lo))
         | ((uint32_t)__bfloat16_as_ushort(__float2bfloat16(e_hi)) << 16);
}
__device__ __forceinline__ void split_pair(float v0, float v1, uint32_t& hi, uint32_t& lo) {
    float h0 = __bfloat162float(__float2bfloat16(v0));
    float h1 = __bfloat162float(__float2bfloat16(v1));
    hi = packbf(v0, v1);
    lo = packbf(v0 - h0, v1 - h1);
}
__device__ __forceinline__ void storeA4(char* sm, int row, int k, float x, float y, float z, float w) {
    uint32_t h0, l0, h1, l1;
    split_pair(x, y, h0, l0);
    split_pair(z, w, h1, l1);
    *(uint2*)(sm + A_HI + row * ASTR + k * 2) = make_uint2(h0, h1);
    *(uint2*)(sm + A_LO + row * ASTR + k * 2) = make_uint2(l0, l1);
}

typedef wmma::fragment<wmma::accumulator, 16, 16, 16, float> AccFrag;

// ---------------- GEMM: [64 x 16K] @ [16K x 32*NFRAG*2]; warp = (rowg = w&3, colh = w>>2) ----
// bf16 split: ah*bh + ah*bl + al*bh, fp32 accumulate. Accums returned in regs.
template<int KSTEPS, int NFRAG>
__device__ __forceinline__ void gemm_wmma(char* sm, int warp, AccFrag* c) {
#pragma unroll
    for (int j = 0; j < NFRAG; j++) wmma::fill_fragment(c[j], 0.f);
    const int rowg = warp & 3, colh = warp >> 2;
    const __nv_bfloat16* Ah = (const __nv_bfloat16*)(sm + A_HI) + 16 * rowg * LDM;
    const __nv_bfloat16* Al = (const __nv_bfloat16*)(sm + A_LO) + 16 * rowg * LDM;
    const __nv_bfloat16* Bh = (const __nv_bfloat16*)(sm + B_HI);
    const __nv_bfloat16* Bl = (const __nv_bfloat16*)(sm + B_LO);
#pragma unroll
    for (int ks = 0; ks < KSTEPS; ks++) {
        wmma::fragment<wmma::matrix_a, 16, 16, 16, __nv_bfloat16, wmma::row_major> ah, al;
        wmma::load_matrix_sync(ah, Ah + ks * 16, LDM);
        wmma::load_matrix_sync(al, Al + ks * 16, LDM);
#pragma unroll
        for (int j = 0; j < NFRAG; j++) {
            const int n0 = colh * NFRAG + j;
            wmma::fragment<wmma::matrix_b, 16, 16, 16, __nv_bfloat16, wmma::col_major> bh, bl;
            wmma::load_matrix_sync(bh, Bh + n0 * 16 * LDM + ks * 16, LDM);
            wmma::load_matrix_sync(bl, Bl + n0 * 16 * LDM + ks * 16, LDM);
            wmma::mma_sync(c[j], ah, bh, c[j]);
            wmma::mma_sync(c[j], ah, bl, c[j]);
            wmma::mma_sync(c[j], al, bh, c[j]);
        }
    }
}

// store accums into C scratch (aliases B_LO) — call AFTER __syncthreads (B fully consumed)
template<int NFRAG>
__device__ __forceinline__ void storeC(char* sm, int warp, AccFrag* c) {
    const int rowg = warp & 3, colh = warp >> 2;
    float* C = (float*)(sm + B_LO) + 16 * rowg * LDM;
#pragma unroll
    for (int j = 0; j < NFRAG; j++)
        wmma::store_matrix_sync(C + (colh * NFRAG + j) * 16, c[j], LDM, wmma::mem_row_major);
}

// C (64x128) -> relu -> hi/lo split back into A tile
__device__ __forceinline__ void resplitA(char* sm, int tid) {
    int row = tid >> 2, seg = tid & 3;
    const float* C = (const float*)(sm + B_LO) + row * LDM + seg * 32;
#pragma unroll
    for (int f = 0; f < 8; f++) {
        float4 v = *(const float4*)(C + f * 4);
        storeA4(sm, row, seg * 32 + f * 4,
                fmaxf(v.x, 0.f), fmaxf(v.y, 0.f), fmaxf(v.z, 0.f), fmaxf(v.w, 0.f));
    }
}

__device__ __forceinline__ void loadB(char* sm, int wd, int cnt16, int tid) {
    const uint4* sH = (const uint4*)(g_whi + wd);
    const uint4* sL = (const uint4*)(g_wlo + wd);
    uint4* dH = (uint4*)(sm + B_HI);
    uint4* dL = (uint4*)(sm + B_LO);
    for (int i = tid; i < cnt16; i += 256) { dH[i] = sH[i]; dL[i] = sL[i]; }
}

// ---------------- weight prep (unchanged layout): Bt n-major, k-contiguous, 272B stride ----------
struct WPtrs { const float* w[18]; };
__device__ const short P_widx[30] = {4,5,7,8, 9,9,9,9, 10,10,10,10, 11,11,11,11,
                                     12,12,12,12, 13,13,13,13, 14,14,14,14, 15,16};
__device__ const int   P_soff[30] = {0,0,0,0, 0,12288,24576,36864, 0,16384,32768,49152,
                                     0,4096,8192,12288, 0,8192,16384,24576,
                                     0,16384,32768,49152, 0,4096,8192,12288, 0,0};
__device__ const short P_K[30] = {128,128,128,128, 96,96,96,96, 128,128,128,128, 128,128,128,128,
                                  64,64,64,64, 128,128,128,128, 128,128,128,128, 32,128};
__device__ const short P_N[30] = {128,32,128,32, 128,128,128,128, 128,128,128,128, 32,32,32,32,
                                  128,128,128,128, 128,128,128,128, 32,32,32,32, 128,128};
__device__ const int   P_dst[30] = {0,34816,43520,78336,
                                    87040,165376,243712,322048,
                                    121856,200192,278528,356864,
                                    156672,235008,313344,391680,
                                    400384,478720,557056,635392,
                                    435200,513536,591872,670208,
                                    470016,548352,626688,705024,
                                    713728,748544};

__global__ void __launch_bounds__(256) prep_kernel(WPtrs P) {
    int b = blockIdx.x, t = 0, start = 0;
    for (; t < 30; t++) { int nb = (int)P_K[t] * (int)P_N[t] / 256; if (b < start + nb) break; start += nb; }
    int e = (b - start) * 256 + threadIdx.x;
    int N = P_N[t];
    int k = e / N, n = e % N;
    float v = P.w[P_widx[t]][P_soff[t] + e];
    __nv_bfloat16 h = __float2bfloat16(v);
    __nv_bfloat16 l = __float2bfloat16(v - __bfloat162float(h));
    int off = P_dst[t] + n * ASTR + k * 2;
    *(unsigned short*)(g_whi + off) = __bfloat16_as_ushort(h);
    *(unsigned short*)(g_wlo + off) = __bfloat16_as_ushort(l);
}

__global__ void zero_agg_kernel() {
    int i = blockIdx.x * 256 + threadIdx.x;
    ((float4*)g_agg)[i] = make_float4(0.f, 0.f, 0.f, 0.f);
}

// ---------------- fused MLP; MODE: 0=ENC_N 1=ENC_E 2=EDGE 3=NODE 4=DEC; 64 rows/block ----------
template<int MODE>
__global__ void __launch_bounds__(256) mlp_mma(const float* __restrict__ in,
                                               const int* __restrict__ gi,
                                               const float* __restrict__ wraw,
                                               float* __restrict__ out,
                                               int wd0, int wd1, int wd2) {
    extern __shared__ char sm[];
    const int tid = threadIdx.x;
    const int warp = tid >> 5;
    const int b0 = blockIdx.x * 64;
    const int row = tid >> 2, seg = tid & 3;

    // ---------- build A tile (64 x K) ----------
    if (MODE == 2) {
        if (tid < 128) ((int*)(sm + S_IDX))[tid] = gi[b0 * 2 + tid];
        __syncthreads();
        int s_ = ((int*)(sm + S_IDX))[row * 2 + 0];
        int r_ = ((int*)(sm + S_IDX))[row * 2 + 1];
#pragma unroll
        for (int f = 0; f < 6; f++) {
            int k = seg * 24 + f * 4;
            const float* src = (k < 32) ? (g_edge + (size_t)(b0 + row) * 32 + k)
                             : (k < 64) ? (g_node + (size_t)s_ * 32 + (k - 32))
                                        : (g_node + (size_t)r_ * 32 + (k - 64));
            float4 v = *(const float4*)src;
            storeA4(sm, row, k, v.x, v.y, v.z, v.w);
        }
    } else if (MODE == 3) {
#pragma unroll
        for (int f = 0; f < 4; f++) {
            int k = seg * 16 + f * 4;
            const float* src = (k < 32) ? (g_node + (size_t)(b0 + row) * 32 + k)
                                        : (g_agg  + (size_t)(b0 + row) * 32 + (k - 32));
            float4 v = *(const float4*)src;
            storeA4(sm, row, k, v.x, v.y, v.z, v.w);
        }
    } else if (MODE == 4) {
        if (tid < 128) ((float*)(sm + S_W0))[tid] = wraw[tid];
#pragma unroll
        for (int f = 0; f < 2; f++) {
            int k = seg * 8 + f * 4;
            float4 v = *(const float4*)(g_node + (size_t)(b0 + row) * 32 + k);
            storeA4(sm, row, k, v.x, v.y, v.z, v.w);
        }
    } else {  // encoders: SIMT layer0 (3 -> 128) + relu
        for (int i = tid; i < 384; i += 256)
            ((float*)(sm + S_W0))[i] = wraw[i];
        __syncthreads();
        float x0 = in[(b0 + row) * 3 + 0];
        float x1 = in[(b0 + row) * 3 + 1];
        float x2 = in[(b0 + row) * 3 + 2];
        const float* W0 = (const float*)(sm + S_W0);
#pragma unroll
        for (int f = 0; f < 8; f++) {
            int c = seg * 32 + f * 4;
            float h0 = fmaxf(fmaf(x0, W0[c + 0], fmaf(x1, W0[128 + c + 0], x2 * W0[256 + c + 0])), 0.f);
            float h1 = fmaxf(fmaf(x0, W0[c + 1], fmaf(x1, W0[128 + c + 1], x2 * W0[256 + c + 1])), 0.f);
            float h2 = fmaxf(fmaf(x0, W0[c + 2], fmaf(x1, W0[128 + c + 2], x2 * W0[256 + c + 2])), 0.f);
            float h3 = fmaxf(fmaf(x0, W0[c + 3], fmaf(x1, W0[128 + c + 3], x2 * W0[256 + c + 3])), 0.f);
            storeA4(sm, row, c, h0, h1, h2, h3);
        }
    }

    AccFrag c[4];

    if (MODE == 2 || MODE == 3) {
        loadB(sm, wd0, 128 * 17, tid);
        __syncthreads();
        if (MODE == 2) gemm_wmma<6, 4>(sm, warp, c);
        else           gemm_wmma<4, 4>(sm, warp, c);
        __syncthreads();
        storeC<4>(sm, warp, c);
        __syncthreads();
        resplitA(sm, tid);
        __syncthreads();
        loadB(sm, wd1, 128 * 17, tid);
        __syncthreads();
        gemm_wmma<8, 4>(sm, warp, c);
        __syncthreads();
        storeC<4>(sm, warp, c);
        __syncthreads();
        resplitA(sm, tid);
        __syncthreads();
        loadB(sm, wd2, 32 * 17, tid);
        __syncthreads();
        gemm_wmma<8, 1>(sm, warp, c);
        __syncthreads();
        storeC<1>(sm, warp, c);
        __syncthreads();
        // epilogue: residual (+ scatter for edges); thread = (row, 8 cols at seg*8)
        const float* C = (const float*)(sm + B_LO) + row * LDM + seg * 8;
        float* dst = (MODE == 2) ? g_edge : g_node;
        float* pe = dst + (size_t)(b0 + row) * 32 + seg * 8;
        int rcv = (MODE == 2) ? ((int*)(sm + S_IDX))[row * 2 + 1] : 0;
        float* pa = g_agg + (size_t)rcv * 32 + seg * 8;
#pragma unroll
        for (int f = 0; f < 2; f++) {
            float4 cc = *(const float4*)(C + f * 4);
            float4 o  = *(const float4*)(pe + f * 4);
            float v0 = cc.x + o.x, v1 = cc.y + o.y, v2 = cc.z + o.z, v3 = cc.w + o.w;
            *(float4*)(pe + f * 4) = make_float4(v0, v1, v2, v3);
            if (MODE == 2) {
                atomicAdd(pa + f * 4 + 0, v0);
                atomicAdd(pa + f * 4 + 1, v1);
                atomicAdd(pa + f * 4 + 2, v2);
                atomicAdd(pa + f * 4 + 3, v3);
            }
        }
    } else if (MODE == 0 || MODE == 1) {
        loadB(sm, wd0, 128 * 17, tid);   // w1: 128x128
        __syncthreads();
        gemm_wmma<8, 4>(sm, warp, c);
        __syncthreads();
        storeC<4>(sm, warp, c);
        __syncthreads();
        resplitA(sm, tid);
        __syncthreads();
        loadB(sm, wd1, 32 * 17, tid);    // w2: 128->32
        __syncthreads();
        gemm_wmma<8, 1>(sm, warp, c);
        __syncthreads();
        storeC<1>(sm, warp, c);
        __syncthreads();
        const float* C = (const float*)(sm + B_LO) + row * LDM + seg * 8;
        float* dst = ((MODE == 0) ? g_node : g_edge) + (size_t)(b0 + row) * 32 + seg * 8;
#pragma unroll
        for (int f = 0; f < 2; f++)
            *(float4*)(dst + f * 4) = *(const float4*)(C + f * 4);
    } else {  // DEC
        loadB(sm, wd0, 128 * 17, tid);   // w0: 32->128
        __syncthreads();
        gemm_wmma<2, 4>(sm, warp, c);
        __syncthreads();
        storeC<4>(sm, warp, c);
        __syncthreads();
        resplitA(sm, tid);
        __syncthreads();
        loadB(sm, wd1, 128 * 17, tid);   // w1: 128x128
        __syncthreads();
        gemm_wmma<8, 4>(sm, warp, c);
        __syncthreads();
        storeC<4>(sm, warp, c);
        __syncthreads();
        const float* C = (const float*)(sm + B_LO) + row * LDM + seg * 32;
        const float* W2 = (const float*)(sm + S_W0) + seg * 32;
        float partial = 0.f;
#pragma unroll
        for (int f = 0; f < 8; f++) {
            float4 c4 = *(const float4*)(C + f * 4);
            float4 w4 = *(const float4*)(W2 + f * 4);
            partial = fmaf(fmaxf(c4.x, 0.f), w4.x, partial);
            partial = fmaf(fmaxf(c4.y, 0.f), w4.y, partial);
            partial = fmaf(fmaxf(c4.z, 0.f), w4.z, partial);
            partial = fmaf(fmaxf(c4.w, 0.f), w4.w, partial);
        }
        partial += __shfl_xor_sync(0xFFFFFFFFu, partial, 1);
        partial += __shfl_xor_sync(0xFFFFFFFFu, partial, 2);
        if (seg == 0) out[b0 + row] = partial;
    }
}

// ---------------- launch ----------------
extern "C" void kernel_launch(void* const* d_in, const int* in_sizes, int n_in,
                              void* d_out, int out_size) {
    WPtrs P;
    for (int i = 0; i < 18; i++) P.w[i] = (const float*)d_in[i];
    const float* input_node = (const float*)d_in[0];
    const float* input_edge = (const float*)d_in[1];
    const int*   gi         = (const int*)d_in[2];
    float* out = (float*)d_out;

    cudaFuncSetAttribute(mlp_mma<0>, cudaFuncAttributeMaxDynamicSharedMemorySize, SM_DYN);
    cudaFuncSetAttribute(mlp_mma<1>, cudaFuncAttributeMaxDynamicSharedMemorySize, SM_DYN);
    cudaFuncSetAttribute(mlp_mma<2>, cudaFuncAttributeMaxDynamicSharedMemorySize, SM_DYN);
    cudaFuncSetAttribute(mlp_mma<3>, cudaFuncAttributeMaxDynamicSharedMemorySize, SM_DYN);
    cudaFuncSetAttribute(mlp_mma<4>, cudaFuncAttributeMaxDynamicSharedMemorySize, SM_DYN);

    prep_kernel<<<1200, 256>>>(P);

    mlp_mma<0><<<NN / 64, 256, SM_DYN>>>(input_node, nullptr, (const float*)d_in[3], nullptr,
                                         0, 34816, 0);
    mlp_mma<1><<<NE / 64, 256, SM_DYN>>>(input_edge, nullptr, (const float*)d_in[6], nullptr,
                                         43520, 78336, 0);

    for (int it = 0; it < 4; it++) {
        zero_agg_kernel<<<NN * 32 / 4 / 256, 256>>>();
        mlp_mma<2><<<NE / 64, 256, SM_DYN>>>(nullptr, gi, nullptr, nullptr,
                                             87040 + it * 78336,
                                             121856 + it * 78336,
                                             156672 + it * 78336);
        mlp_mma<3><<<NN / 64, 256, SM_DYN>>>(nullptr, nullptr, nullptr, nullptr,
                                             400384 + it * 78336,
                                             435200 + it * 78336,
                                             470016 + it * 78336);
    }
    mlp_mma<4><<<NN / 64, 256, SM_DYN>>>(nullptr, nullptr, (const float*)d_in[17], out,
                                         713728, 748544, 0);
}

// round 11
// speedup vs baseline: 3.5801x; 2.6253x over previous
#include <cuda_runtime.h>
#include <cuda_bf16.h>
#include <stdint.h>

#define NN 32000
#define NE 512000

// ---------------- persistent device scratch ----------------
__device__ float g_node[NN * 32];
__device__ float g_edge[NE * 32];
__device__ float g_agg [NN * 32];
__device__ __align__(16) unsigned char g_whi[786432];
__device__ __align__(16) unsigned char g_wlo[786432];

// smem byte offsets (64-row tiles)
#define A_HI 0               // 64 x 272
#define A_LO 17408
#define B_HI 34816           // up to 128 n-rows x 272
#define B_LO 69632
#define S_IDX 104448         // 128 ints (also DEC row-reduce buffer)
#define S_W0  104960         // 384 floats
#define SM_DYN 106496
#define ASTR 272             // row stride bytes (136 bf16 / 68 words)

__device__ __forceinline__ uint32_t smem_u32(const void* p) {
    uint32_t a;
    asm("{ .reg .u64 t; cvta.to.shared.u64 t, %1; cvt.u32.u64 %0, t; }" : "=r"(a) : "l"(p));
    return a;
}

#define LDSM4(d, addr) \
    asm volatile("ldmatrix.sync.aligned.m8n8.x4.shared.b16 {%0,%1,%2,%3}, [%4];" \
        : "=r"((d)[0]), "=r"((d)[1]), "=r"((d)[2]), "=r"((d)[3]) : "r"(addr))

#define MMA816(c, a, b0, b1) \
    asm volatile("mma.sync.aligned.m16n8k16.row.col.f32.bf16.bf16.f32 " \
        "{%0,%1,%2,%3}, {%4,%5,%6,%7}, {%8,%9}, {%0,%1,%2,%3};" \
        : "+f"((c)[0]), "+f"((c)[1]), "+f"((c)[2]), "+f"((c)[3]) \
        : "r"((a)[0]), "r"((a)[1]), "r"((a)[2]), "r"((a)[3]), "r"(b0), "r"(b1))

#define CP16(dst, src) \
    asm volatile("cp.async.cg.shared.global [%0], [%1], 16;" :: "r"(dst), "l"(src))
#define CP_COMMIT() asm volatile("cp.async.commit_group;" ::: "memory")
#define CP_WAIT0()  asm volatile("cp.async.wait_group 0;" ::: "memory")

// pack two bf16: lower k index in lower 16 bits
__device__ __forceinline__ uint32_t packbf(float e_lo, float e_hi) {
    return (uint32_t)__bfloat16_as_ushort(__float2bfloat16(e_lo))
         | ((uint32_t)__bfloat16_as_ushort(__float2bfloat16(e_hi)) << 16);
}
__device__ __forceinline__ void split_pair(float v0, float v1, uint32_t& hi, uint32_t& lo) {
    float h0 = __bfloat162float(__float2bfloat16(v0));
    float h1 = __bfloat162float(__float2bfloat16(v1));
    hi = packbf(v0, v1);
    lo = packbf(v0 - h0, v1 - h1);
}
__device__ __forceinline__ void storeA4(char* sm, int row, int k, float x, float y, float z, float w) {
    uint32_t h0, l0, h1, l1;
    split_pair(x, y, h0, l0);
    split_pair(z, w, h1, l1);
    *(uint2*)(sm + A_HI + row * ASTR + k * 2) = make_uint2(h0, h1);
    *(uint2*)(sm + A_LO + row * ASTR + k * 2) = make_uint2(l0, l1);
}

// async copy of pre-split weight tiles into B_HI/B_LO
__device__ __forceinline__ void loadB_async(uint32_t smb, int wd, int cnt16, int tid) {
    const char* gH = (const char*)g_whi + wd;
    const char* gL = (const char*)g_wlo + wd;
    uint32_t dH = smb + B_HI, dL = smb + B_LO;
    for (int i = tid; i < cnt16; i += 256) {
        CP16(dH + i * 16, gH + (size_t)i * 16);
        CP16(dL + i * 16, gL + (size_t)i * 16);
    }
}

// ---------------- GEMM: warp tile (MT*16 rows) x (NT8*8 cols), bf16 split, fp32 acc -----------
// MT==2: rowg=warp&1 (R0=32*rowg), colh=warp>>1 (N0=32*colh), NT8=4  -> N=128 layers
// MT==1: rowg=warp&3 (R0=16*rowg), colh=warp>>2 (N0=16*colh), NT8=2  -> N=32 layers
// Fragment addressing validated in R4/R5/R6 fingerprint experiment.
template<int KSTEPS, int MT, int NT8>
__device__ __forceinline__ void gemm(uint32_t smb, int warp, int lane, float (*acc)[4]) {
#pragma unroll
    for (int i = 0; i < MT * NT8; i++) { acc[i][0] = 0.f; acc[i][1] = 0.f; acc[i][2] = 0.f; acc[i][3] = 0.f; }
    const int R0 = (MT == 2) ? (warp & 1) * 32 : (warp & 3) * 16;
    const int N0 = (MT == 2) ? (warp >> 1) * 32 : (warp >> 2) * 16;
    const int m = lane >> 3, r = lane & 7;
    const uint32_t aBase = smb + A_HI + (uint32_t)((R0 + r + (m & 1) * 8) * ASTR + (m >> 1) * 16);
    const uint32_t bBase = smb + B_HI + (uint32_t)((N0 + r + ((m >> 1) << 3)) * ASTR + (m & 1) * 16);
#pragma unroll
    for (int ks = 0; ks < KSTEPS; ks++) {
        uint32_t aH[MT][4], aL[MT][4];
#pragma unroll
        for (int mt = 0; mt < MT; mt++) {
            LDSM4(aH[mt], aBase + mt * 16 * ASTR + ks * 32);
            LDSM4(aL[mt], aBase + (A_LO - A_HI) + mt * 16 * ASTR + ks * 32);
        }
#pragma unroll
        for (int gb = 0; gb < NT8 / 2; gb++) {
            uint32_t bH[4], bL[4];
            LDSM4(bH, bBase + gb * 16 * ASTR + ks * 32);
            LDSM4(bL, bBase + (B_LO - B_HI) + gb * 16 * ASTR + ks * 32);
#pragma unroll
            for (int mt = 0; mt < MT; mt++) {
                float* c0 = acc[mt * NT8 + 2 * gb];
                float* c1 = acc[mt * NT8 + 2 * gb + 1];
                MMA816(c0, aH[mt], bH[0], bH[1]);
                MMA816(c1, aH[mt], bH[2], bH[3]);
                MMA816(c0, aH[mt], bL[0], bL[1]);
                MMA816(c1, aH[mt], bL[2], bL[3]);
                MMA816(c0, aL[mt], bH[0], bH[1]);
                MMA816(c1, aL[mt], bH[2], bH[3]);
            }
        }
    }
}

// register epilogue: relu + bf16 split straight from accumulators into A tile (MT=2/NT8=4 only)
// acc[mt*4+j]: c0,c1 -> (R0+16mt+g, N0+8j+2t..+1); c2,c3 -> row +8
__device__ __forceinline__ void writebackA(char* sm, int warp, int lane, float (*acc)[4]) {
    const int R0 = (warp & 1) * 32, N0 = (warp >> 1) * 32;
    const int g = lane >> 2, t = lane & 3;
#pragma unroll
    for (int mt = 0; mt < 2; mt++) {
        int ra = R0 + 16 * mt + g;
#pragma unroll
        for (int j = 0; j < 4; j++) {
            const float* a = acc[mt * 4 + j];
            int c = N0 + 8 * j + 2 * t;
            uint32_t hi, lo;
            split_pair(fmaxf(a[0], 0.f), fmaxf(a[1], 0.f), hi, lo);
            *(uint32_t*)(sm + A_HI + ra * ASTR + c * 2) = hi;
            *(uint32_t*)(sm + A_LO + ra * ASTR + c * 2) = lo;
            split_pair(fmaxf(a[2], 0.f), fmaxf(a[3], 0.f), hi, lo);
            *(uint32_t*)(sm + A_HI + (ra + 8) * ASTR + c * 2) = hi;
            *(uint32_t*)(sm + A_LO + (ra + 8) * ASTR + c * 2) = lo;
        }
    }
}

// ---------------- weight prep (layout unchanged): Bt n-major, k-contiguous, 272B stride --------
struct WPtrs { const float* w[18]; };
__device__ const short P_widx[30] = {4,5,7,8, 9,9,9,9, 10,10,10,10, 11,11,11,11,
                                     12,12,12,12, 13,13,13,13, 14,14,14,14, 15,16};
__device__ const int   P_soff[30] = {0,0,0,0, 0,12288,24576,36864, 0,16384,32768,49152,
                                     0,4096,8192,12288, 0,8192,16384,24576,
                                     0,16384,32768,49152, 0,4096,8192,12288, 0,0};
__device__ const short P_K[30] = {128,128,128,128, 96,96,96,96, 128,128,128,128, 128,128,128,128,
                                  64,64,64,64, 128,128,128,128, 128,128,128,128, 32,128};
__device__ const short P_N[30] = {128,32,128,32, 128,128,128,128, 128,128,128,128, 32,32,32,32,
                                  128,128,128,128, 128,128,128,128, 32,32,32,32, 128,128};
__device__ const int   P_dst[30] = {0,34816,43520,78336,
                                    87040,165376,243712,322048,
                                    121856,200192,278528,356864,
                                    156672,235008,313344,391680,
                                    400384,478720,557056,635392,
                                    435200,513536,591872,670208,
                                    470016,548352,626688,705024,
                                    713728,748544};

__global__ void __launch_bounds__(256) prep_kernel(WPtrs P) {
    int b = blockIdx.x, t = 0, start = 0;
    for (; t < 30; t++) { int nb = (int)P_K[t] * (int)P_N[t] / 256; if (b < start + nb) break; start += nb; }
    int e = (b - start) * 256 + threadIdx.x;
    int N = P_N[t];
    int k = e / N, n = e % N;
    float v = P.w[P_widx[t]][P_soff[t] + e];
    __nv_bfloat16 h = __float2bfloat16(v);
    __nv_bfloat16 l = __float2bfloat16(v - __bfloat162float(h));
    int off = P_dst[t] + n * ASTR + k * 2;
    *(unsigned short*)(g_whi + off) = __bfloat16_as_ushort(h);
    *(unsigned short*)(g_wlo + off) = __bfloat16_as_ushort(l);
}

__global__ void zero_agg_kernel() {
    int i = blockIdx.x * 256 + threadIdx.x;
    ((float4*)g_agg)[i] = make_float4(0.f, 0.f, 0.f, 0.f);
}

// ---------------- fused MLP; MODE: 0=ENC_N 1=ENC_E 2=EDGE 3=NODE 4=DEC; 64 rows/block ----------
template<int MODE>
__global__ void __launch_bounds__(256) mlp_mma(const float* __restrict__ in,
                                               const int* __restrict__ gi,
                                               const float* __restrict__ wraw,
                                               float* __restrict__ out,
                                               int wd0, int wd1, int wd2) {
    extern __shared__ char sm[];
    const uint32_t smb = smem_u32(sm);
    const int tid = threadIdx.x;
    const int warp = tid >> 5, lane = tid & 31;
    const int b0 = blockIdx.x * 64;
    const int row = tid >> 2, seg = tid & 3;

    // prefetch first weight layer while building A
    loadB_async(smb, wd0, 128 * 17, tid);
    CP_COMMIT();

    // ---------- build A tile (64 x K) ----------
    if (MODE == 2) {
        if (tid < 128) ((int*)(sm + S_IDX))[tid] = gi[b0 * 2 + tid];
        __syncthreads();
        int s_ = ((int*)(sm + S_IDX))[row * 2 + 0];
        int r_ = ((int*)(sm + S_IDX))[row * 2 + 1];
#pragma unroll
        for (int f = 0; f < 6; f++) {
            int k = seg * 24 + f * 4;
            const float* src = (k < 32) ? (g_edge + (size_t)(b0 + row) * 32 + k)
                             : (k < 64) ? (g_node + (size_t)s_ * 32 + (k - 32))
                                        : (g_node + (size_t)r_ * 32 + (k - 64));
            float4 v = *(const float4*)src;
            storeA4(sm, row, k, v.x, v.y, v.z, v.w);
        }
    } else if (MODE == 3) {
#pragma unroll
        for (int f = 0; f < 4; f++) {
            int k = seg * 16 + f * 4;
            const float* src = (k < 32) ? (g_node + (size_t)(b0 + row) * 32 + k)
                                        : (g_agg  + (size_t)(b0 + row) * 32 + (k - 32));
            float4 v = *(const float4*)src;
            storeA4(sm, row, k, v.x, v.y, v.z, v.w);
        }
    } else if (MODE == 4) {
        if (tid < 128) ((float*)(sm + S_W0))[tid] = wraw[tid];
        if (tid < 64)  ((float*)(sm + S_IDX))[tid] = 0.f;    // row-reduce buffer
#pragma unroll
        for (int f = 0; f < 2; f++) {
            int k = seg * 8 + f * 4;
            float4 v = *(const float4*)(g_node + (size_t)(b0 + row) * 32 + k);
            storeA4(sm, row, k, v.x, v.y, v.z, v.w);
        }
    } else {  // encoders: SIMT layer0 (3 -> 128) + relu
        for (int i = tid; i < 384; i += 256)
            ((float*)(sm + S_W0))[i] = wraw[i];
        __syncthreads();
        float x0 = in[(b0 + row) * 3 + 0];
        float x1 = in[(b0 + row) * 3 + 1];
        float x2 = in[(b0 + row) * 3 + 2];
        const float* W0 = (const float*)(sm + S_W0);
#pragma unroll
        for (int f = 0; f < 8; f++) {
            int c = seg * 32 + f * 4;
            float h0 = fmaxf(fmaf(x0, W0[c + 0], fmaf(x1, W0[128 + c + 0], x2 * W0[256 + c + 0])), 0.f);
            float h1 = fmaxf(fmaf(x0, W0[c + 1], fmaf(x1, W0[128 + c + 1], x2 * W0[256 + c + 1])), 0.f);
            float h2 = fmaxf(fmaf(x0, W0[c + 2], fmaf(x1, W0[128 + c + 2], x2 * W0[256 + c + 2])), 0.f);
            float h3 = fmaxf(fmaf(x0, W0[c + 3], fmaf(x1, W0[128 + c + 3], x2 * W0[256 + c + 3])), 0.f);
            storeA4(sm, row, c, h0, h1, h2, h3);
        }
    }

    float acc[8][4];
    const int g = lane >> 2, t = lane & 3;

    if (MODE == 2 || MODE == 3) {
        CP_WAIT0(); __syncthreads();
        if (MODE == 2) gemm<6, 2, 4>(smb, warp, lane, acc);
        else           gemm<4, 2, 4>(smb, warp, lane, acc);
        __syncthreads();
        loadB_async(smb, wd1, 128 * 17, tid); CP_COMMIT();
        writebackA(sm, warp, lane, acc);
        CP_WAIT0(); __syncthreads();
        gemm<8, 2, 4>(smb, warp, lane, acc);
        __syncthreads();
        loadB_async(smb, wd2, 32 * 17, tid); CP_COMMIT();
        writebackA(sm, warp, lane, acc);
        CP_WAIT0(); __syncthreads();
        gemm<8, 1, 2>(smb, warp, lane, acc);
        // register epilogue: residual (+ scatter for edges). MT=1: R0=16*(warp&3), N0=16*(warp>>2)
        {
            const int R0 = (warp & 3) * 16, N0 = (warp >> 2) * 16;
            float* dst = (MODE == 2) ? g_edge : g_node;
#pragma unroll
            for (int half = 0; half < 2; half++) {
                int r_ = R0 + g + half * 8;
                int rcv = (MODE == 2) ? ((int*)(sm + S_IDX))[r_ * 2 + 1] : 0;
#pragma unroll
                for (int j = 0; j < 2; j++) {
                    int c = N0 + 8 * j + 2 * t;
                    float* pe = dst + (size_t)(b0 + r_) * 32 + c;
                    float2 o = *(float2*)pe;
                    float v0 = acc[j][half * 2 + 0] + o.x;
                    float v1 = acc[j][half * 2 + 1] + o.y;
                    *(float2*)pe = make_float2(v0, v1);
                    if (MODE == 2) {
                        atomicAdd(g_agg + (size_t)rcv * 32 + c,     v0);
                        atomicAdd(g_agg + (size_t)rcv * 32 + c + 1, v1);
                    }
                }
            }
        }
    } else if (MODE == 0 || MODE == 1) {
        CP_WAIT0(); __syncthreads();
        gemm<8, 2, 4>(smb, warp, lane, acc);
        __syncthreads();
        loadB_async(smb, wd1, 32 * 17, tid); CP_COMMIT();
        writebackA(sm, warp, lane, acc);
        CP_WAIT0(); __syncthreads();
        gemm<8, 1, 2>(smb, warp, lane, acc);
        {
            const int R0 = (warp & 3) * 16, N0 = (warp >> 2) * 16;
            float* dst = (MODE == 0) ? g_node : g_edge;
#pragma unroll
            for (int half = 0; half < 2; half++) {
                int r_ = R0 + g + half * 8;
#pragma unroll
                for (int j = 0; j < 2; j++) {
                    int c = N0 + 8 * j + 2 * t;
                    *(float2*)(dst + (size_t)(b0 + r_) * 32 + c) =
                        make_float2(acc[j][half * 2 + 0], acc[j][half * 2 + 1]);
                }
            }
        }
    } else {  // DEC
        CP_WAIT0(); __syncthreads();
        gemm<2, 2, 4>(smb, warp, lane, acc);
        __syncthreads();
        loadB_async(smb, wd1, 128 * 17, tid); CP_COMMIT();
        writebackA(sm, warp, lane, acc);
        CP_WAIT0(); __syncthreads();
        gemm<8, 2, 4>(smb, warp, lane, acc);
        // final dot with w2 from regs; reduce per-row via smem atomics
        {
            const int R0 = (warp & 1) * 32, N0 = (warp >> 1) * 32;
            const float* W2 = (const float*)(sm + S_W0);
            float* sout = (float*)(sm + S_IDX);
#pragma unroll
            for (int mt = 0; mt < 2; mt++) {
                float pa = 0.f, pb = 0.f;
#pragma unroll
                for (int j = 0; j < 4; j++) {
                    int c = N0 + 8 * j + 2 * t;
                    const float* a = acc[mt * 4 + j];
                    pa = fmaf(fmaxf(a[0], 0.f), W2[c], pa);
                    pa = fmaf(fmaxf(a[1], 0.f), W2[c + 1], pa);
                    pb = fmaf(fmaxf(a[2], 0.f), W2[c], pb);
                    pb = fmaf(fmaxf(a[3], 0.f), W2[c + 1], pb);
                }
                atomicAdd(&sout[R0 + 16 * mt + g], pa);
                atomicAdd(&sout[R0 + 16 * mt + g + 8], pb);
            }
            __syncthreads();
            if (tid < 64) out[b0 + tid] = sout[tid];
        }
    }
}

// ---------------- launch ----------------
extern "C" void kernel_launch(void* const* d_in, const int* in_sizes, int n_in,
                              void* d_out, int out_size) {
    WPtrs P;
    for (int i = 0; i < 18; i++) P.w[i] = (const float*)d_in[i];
    const float* input_node = (const float*)d_in[0];
    const float* input_edge = (const float*)d_in[1];
    const int*   gi         = (const int*)d_in[2];
    float* out = (float*)d_out;

    cudaFuncSetAttribute(mlp_mma<0>, cudaFuncAttributeMaxDynamicSharedMemorySize, SM_DYN);
    cudaFuncSetAttribute(mlp_mma<1>, cudaFuncAttributeMaxDynamicSharedMemorySize, SM_DYN);
    cudaFuncSetAttribute(mlp_mma<2>, cudaFuncAttributeMaxDynamicSharedMemorySize, SM_DYN);
    cudaFuncSetAttribute(mlp_mma<3>, cudaFuncAttributeMaxDynamicSharedMemorySize, SM_DYN);
    cudaFuncSetAttribute(mlp_mma<4>, cudaFuncAttributeMaxDynamicSharedMemorySize, SM_DYN);

    prep_kernel<<<1200, 256>>>(P);

    mlp_mma<0><<<NN / 64, 256, SM_DYN>>>(input_node, nullptr, (const float*)d_in[3], nullptr,
                                         0, 34816, 0);
    mlp_mma<1><<<NE / 64, 256, SM_DYN>>>(input_edge, nullptr, (const float*)d_in[6], nullptr,
                                         43520, 78336, 0);

    for (int it = 0; it < 4; it++) {
        zero_agg_kernel<<<NN * 32 / 4 / 256, 256>>>();
        mlp_mma<2><<<NE / 64, 256, SM_DYN>>>(nullptr, gi, nullptr, nullptr,
                                             87040 + it * 78336,
                                             121856 + it * 78336,
                                             156672 + it * 78336);
        mlp_mma<3><<<NN / 64, 256, SM_DYN>>>(nullptr, nullptr, nullptr, nullptr,
                                             400384 + it * 78336,
                                             435200 + it * 78336,
                                             470016 + it * 78336);
    }
    mlp_mma<4><<<NN / 64, 256, SM_DYN>>>(nullptr, nullptr, (const float*)d_in[17], out,
                                         713728, 748544, 0);
}